// round 2
// baseline (speedup 1.0000x reference)
#include <cuda_runtime.h>
#include <cstdint>

// ---------------------------------------------------------------------------
// GNBlock: h = BN(PReLU(segment_sum(relu(x[src]@W1+b1)@W2+b2, dst) + x@W_root + b_root))
// N=50000, E=800000, C_IN=64, C_HID=128, C_OUT=64
// ---------------------------------------------------------------------------

#define N_MAX 50000
#define C_IN 64
#define C_HID 128
#define C_OUT 64
#define TILE_E 64
#define NT 256

// scratch (static device allocations are allowed)
__device__ __align__(16) float g_h[N_MAX * C_OUT];
__device__ float g_stats[2 * C_OUT];  // [0:64) sum, [64:128) sumsq
__device__ int g_idx64;               // 1 if edge_index is int64, 0 if int32

// ---- f32x2 packed helpers (FFMA2 path, PTX-only on sm_103a) ----------------
__device__ __forceinline__ unsigned long long pack2(float v) {
    unsigned long long r;
    unsigned int u = __float_as_uint(v);
    asm("mov.b64 %0, {%1, %2};" : "=l"(r) : "r"(u), "r"(u));
    return r;
}
__device__ __forceinline__ unsigned long long fma2(unsigned long long a,
                                                   unsigned long long b,
                                                   unsigned long long c) {
    unsigned long long d;
    asm("fma.rn.f32x2 %0, %1, %2, %3;" : "=l"(d) : "l"(a), "l"(b), "l"(c));
    return d;
}
__device__ __forceinline__ float2 unpack2(unsigned long long v) {
    unsigned int lo, hi;
    asm("mov.b64 {%0, %1}, %2;" : "=r"(lo), "=r"(hi) : "l"(v));
    float2 f;
    f.x = __uint_as_float(lo);
    f.y = __uint_as_float(hi);
    return f;
}

// ---------------------------------------------------------------------------
// K0: probe edge_index element width. If the buffer is true int64, the first
// 32 values (little-endian, high word 0) are all in [0, N). If it is int32,
// an int64-read packs two random indices -> astronomically out of range.
// ---------------------------------------------------------------------------
__global__ void detect_kernel(const void* __restrict__ ei, int N) {
    if (threadIdx.x == 0 && blockIdx.x == 0) {
        const long long* p = (const long long*)ei;
        int ok = 1;
        for (int j = 0; j < 32; j++) {
            long long v = p[j];
            if (v < 0 || v >= (long long)N) { ok = 0; break; }
        }
        g_idx64 = ok;
    }
}

// ---------------------------------------------------------------------------
// K1: node transform h[n] = x[n] @ W_root + b_root  (also zero stats)
// ---------------------------------------------------------------------------
__global__ void node_kernel(const float* __restrict__ x,
                            const float* __restrict__ Wr,
                            const float* __restrict__ br, int N) {
    if (blockIdx.x == 0 && threadIdx.x < 2 * C_OUT) g_stats[threadIdx.x] = 0.f;
    int gid = blockIdx.x * NT + threadIdx.x;
    if (gid >= N * C_OUT) return;
    int n = gid >> 6;
    int c = gid & 63;
    const float* xr = x + (long long)n * C_IN;
    float acc = br[c];
#pragma unroll 16
    for (int i = 0; i < C_IN; i++) acc = fmaf(xr[i], Wr[i * C_OUT + c], acc);
    g_h[gid] = acc;
}

// ---------------------------------------------------------------------------
// K2: per-edge message MLP (tile of 64 edges per block) + scatter-add
// smem layout (floats): W1[64*128] W2[128*64] X[64*68] H[64*132] b1[128] b2[64]
// ---------------------------------------------------------------------------
#define SX_PITCH 68
#define SH_PITCH 132
#define SMEM_FLOATS (8192 + 8192 + TILE_E * SX_PITCH + TILE_E * SH_PITCH + 128 + 64)
#define SMEM_BYTES (SMEM_FLOATS * 4)

__global__ __launch_bounds__(NT) void edge_kernel(
    const float* __restrict__ x, const void* __restrict__ ei_raw,
    const float* __restrict__ W1, const float* __restrict__ b1,
    const float* __restrict__ W2, const float* __restrict__ b2, int E) {
    extern __shared__ float sm[];
    float* sW1 = sm;                      // 64 x 128
    float* sW2 = sW1 + 64 * 128;          // 128 x 64
    float* sX = sW2 + 128 * 64;           // 64 x 68 (padded)
    float* sH = sX + TILE_E * SX_PITCH;   // 64 x 132 (padded)
    float* sb1 = sH + TILE_E * SH_PITCH;  // 128
    float* sb2 = sb1 + 128;               // 64
    __shared__ int sSrc[TILE_E];
    __shared__ int sDst[TILE_E];

    const int tid = threadIdx.x;
    const int e0 = blockIdx.x * TILE_E;

    // stage weights + biases + edge indices
    for (int i = tid; i < 2048; i += NT)
        reinterpret_cast<float4*>(sW1)[i] = reinterpret_cast<const float4*>(W1)[i];
    for (int i = tid; i < 2048; i += NT)
        reinterpret_cast<float4*>(sW2)[i] = reinterpret_cast<const float4*>(W2)[i];
    if (tid < 128) sb1[tid] = b1[tid];
    if (tid < 64) sb2[tid] = b2[tid];
    if (tid < TILE_E) {
        int e = e0 + tid;
        if (e < E) {
            if (g_idx64) {
                const long long* p = (const long long*)ei_raw;
                sSrc[tid] = (int)p[e];
                sDst[tid] = (int)p[E + e];
            } else {
                const int* p = (const int*)ei_raw;
                sSrc[tid] = p[e];
                sDst[tid] = p[E + e];
            }
        } else {
            sSrc[tid] = 0;
            sDst[tid] = -1;
        }
    }
    __syncthreads();

    // stage X tile (gather rows of x; x rows are 256B, L2-resident)
    for (int i = tid; i < TILE_E * 16; i += NT) {
        int e = i >> 4, q = i & 15;
        float4 v = reinterpret_cast<const float4*>(x + (long long)sSrc[e] * C_IN)[q];
        *reinterpret_cast<float4*>(&sX[e * SX_PITCH + q * 4]) = v;
    }
    __syncthreads();

    // ---- GEMM1: H[64,128] = relu(X[64,64] @ W1[64,128] + b1) ----
    // thread tile: 4 edges x 8 hidden (as 4 f32x2 pairs)
    {
        const int hg = tid & 15;  // hidden group
        const int eg = tid >> 4;  // edge group
        const int hb = hg * 8;
        const int eb = eg * 4;

        unsigned long long acc[4][4];
#pragma unroll
        for (int e = 0; e < 4; e++)
#pragma unroll
            for (int p = 0; p < 4; p++) acc[e][p] = 0ULL;

#pragma unroll 16
        for (int k = 0; k < C_IN; k++) {
            ulonglong2 w0 = *reinterpret_cast<const ulonglong2*>(&sW1[k * C_HID + hb]);
            ulonglong2 w1 = *reinterpret_cast<const ulonglong2*>(&sW1[k * C_HID + hb + 4]);
#pragma unroll
            for (int e = 0; e < 4; e++) {
                unsigned long long xp = pack2(sX[(eb + e) * SX_PITCH + k]);
                acc[e][0] = fma2(xp, w0.x, acc[e][0]);
                acc[e][1] = fma2(xp, w0.y, acc[e][1]);
                acc[e][2] = fma2(xp, w1.x, acc[e][2]);
                acc[e][3] = fma2(xp, w1.y, acc[e][3]);
            }
        }
        // epilogue: bias + relu -> sH
#pragma unroll
        for (int e = 0; e < 4; e++) {
#pragma unroll
            for (int p = 0; p < 4; p++) {
                float2 v = unpack2(acc[e][p]);
                v.x = fmaxf(v.x + sb1[hb + 2 * p], 0.f);
                v.y = fmaxf(v.y + sb1[hb + 2 * p + 1], 0.f);
                *reinterpret_cast<float2*>(&sH[(eb + e) * SH_PITCH + hb + 2 * p]) = v;
            }
        }
    }
    __syncthreads();

    // ---- GEMM2: M[64,64] = H[64,128] @ W2[128,64] + b2 ; scatter-add ----
    // thread tile: 4 edges x 4 outs (2 f32x2 pairs)
    {
        const int kg = tid & 15;
        const int eg = tid >> 4;
        const int kb = kg * 4;
        const int eb = eg * 4;

        unsigned long long a2[4][2];
#pragma unroll
        for (int e = 0; e < 4; e++) {
            a2[e][0] = 0ULL;
            a2[e][1] = 0ULL;
        }

#pragma unroll 16
        for (int j = 0; j < C_HID; j++) {
            ulonglong2 w = *reinterpret_cast<const ulonglong2*>(&sW2[j * C_OUT + kb]);
#pragma unroll
            for (int e = 0; e < 4; e++) {
                unsigned long long hp = pack2(sH[(eb + e) * SH_PITCH + j]);
                a2[e][0] = fma2(hp, w.x, a2[e][0]);
                a2[e][1] = fma2(hp, w.y, a2[e][1]);
            }
        }

        float bx0 = sb2[kb], bx1 = sb2[kb + 1], bx2 = sb2[kb + 2], bx3 = sb2[kb + 3];
#pragma unroll
        for (int e = 0; e < 4; e++) {
            int d = sDst[eb + e];
            if (d < 0) continue;
            float2 v0 = unpack2(a2[e][0]);
            float2 v1 = unpack2(a2[e][1]);
            float r0 = v0.x + bx0, r1 = v0.y + bx1, r2 = v1.x + bx2, r3 = v1.y + bx3;
            float* p = &g_h[(long long)d * C_OUT + kb];
            asm volatile("red.global.add.v4.f32 [%0], {%1,%2,%3,%4};"
                         :: "l"(p), "f"(r0), "f"(r1), "f"(r2), "f"(r3)
                         : "memory");
        }
    }
}

// ---------------------------------------------------------------------------
// K3: PReLU in-place + per-channel sum / sumsq partials
// (grid*block stride is a multiple of 64 -> each thread owns one channel)
// ---------------------------------------------------------------------------
__global__ void prelu_stats_kernel(const float* __restrict__ prelu_w, int N) {
    const float a = prelu_w[0];
    const int total = N * C_OUT;
    const int stride = gridDim.x * blockDim.x;
    float s = 0.f, ss = 0.f;
    for (int i = blockIdx.x * blockDim.x + threadIdx.x; i < total; i += stride) {
        float v = g_h[i];
        v = (v >= 0.f) ? v : a * v;
        g_h[i] = v;
        s += v;
        ss += v * v;
    }
    __shared__ float rs[NT], rss[NT];
    rs[threadIdx.x] = s;
    rss[threadIdx.x] = ss;
    __syncthreads();
    if (threadIdx.x < 64) {
        float ts = rs[threadIdx.x] + rs[threadIdx.x + 64] + rs[threadIdx.x + 128] +
                   rs[threadIdx.x + 192];
        float tss = rss[threadIdx.x] + rss[threadIdx.x + 64] + rss[threadIdx.x + 128] +
                    rss[threadIdx.x + 192];
        atomicAdd(&g_stats[threadIdx.x], ts);
        atomicAdd(&g_stats[64 + threadIdx.x], tss);
    }
}

// ---------------------------------------------------------------------------
// K4: finalize BN and write output
// ---------------------------------------------------------------------------
__global__ void bn_kernel(float* __restrict__ out, const float* __restrict__ gamma,
                          const float* __restrict__ beta, int N) {
    __shared__ float sscale[C_OUT], sshift[C_OUT];
    if (threadIdx.x < C_OUT) {
        float invN = 1.f / (float)N;
        float mu = g_stats[threadIdx.x] * invN;
        float var = g_stats[64 + threadIdx.x] * invN - mu * mu;
        float inv = rsqrtf(var + 1e-5f);
        float g = gamma[threadIdx.x] * inv;
        sscale[threadIdx.x] = g;
        sshift[threadIdx.x] = beta[threadIdx.x] - mu * g;
    }
    __syncthreads();
    const int total = N * C_OUT;
    const int stride = gridDim.x * blockDim.x;
    for (int i = blockIdx.x * blockDim.x + threadIdx.x; i < total; i += stride) {
        out[i] = g_h[i] * sscale[i & 63] + sshift[i & 63];
    }
}

// ---------------------------------------------------------------------------
extern "C" void kernel_launch(void* const* d_in, const int* in_sizes, int n_in,
                              void* d_out, int out_size) {
    const float* x = (const float*)d_in[0];
    const void* ei = d_in[1];
    const float* W1 = (const float*)d_in[2];
    const float* b1 = (const float*)d_in[3];
    const float* W2 = (const float*)d_in[4];
    const float* b2 = (const float*)d_in[5];
    const float* Wr = (const float*)d_in[6];
    const float* br = (const float*)d_in[7];
    const float* pw = (const float*)d_in[8];
    const float* gamma = (const float*)d_in[9];
    const float* beta = (const float*)d_in[10];
    float* out = (float*)d_out;

    const int N = in_sizes[0] / C_IN;
    const int E = in_sizes[1] / 2;

    cudaFuncSetAttribute(edge_kernel, cudaFuncAttributeMaxDynamicSharedMemorySize,
                         SMEM_BYTES);

    // K0: index dtype probe
    detect_kernel<<<1, 32>>>(ei, N);

    // K1: node transform (+ stats zero)
    node_kernel<<<(N * C_OUT + NT - 1) / NT, NT>>>(x, Wr, br, N);

    // K2: edge messages + scatter
    const int numTiles = (E + TILE_E - 1) / TILE_E;
    edge_kernel<<<numTiles, NT, SMEM_BYTES>>>(x, ei, W1, b1, W2, b2, E);

    // K3: PReLU + batch stats
    prelu_stats_kernel<<<592, NT>>>(pw, N);

    // K4: BN normalize -> out
    bn_kernel<<<592, NT>>>(out, gamma, beta, N);
}

// round 3
// speedup vs baseline: 5.7399x; 5.7399x over previous
#include <cuda_runtime.h>
#include <cstdint>

// ---------------------------------------------------------------------------
// GNBlock: h = BN(PReLU(segment_sum(relu(x[src]@W1+b1)@W2+b2, dst) + x@W_root + b_root))
// N=50000, E=800000, C_IN=64, C_HID=128, C_OUT=64
//
// Key insight: message = MLP(x[src]) depends ONLY on the source node.
// Precompute msg[n] for all N nodes (16x less FLOP than per-edge),
// then scatter msg[src] -> h[dst] with vectorized global reductions.
// ---------------------------------------------------------------------------

#define N_MAX 50000
#define C_IN 64
#define C_HID 128
#define C_OUT 64
#define TILE_N 64
#define NT 256

// scratch (static device arrays are allowed)
__device__ __align__(16) float g_h[N_MAX * C_OUT];
__device__ __align__(16) float g_msg[N_MAX * C_OUT];
__device__ float g_stats[2 * C_OUT];  // [0:64) sum, [64:128) sumsq
__device__ int g_idx64;               // 1 if edge_index is int64, 0 if int32

// ---- f32x2 packed helpers (FFMA2 path, PTX-only on sm_103a) ----------------
__device__ __forceinline__ unsigned long long pack2(float v) {
    unsigned long long r;
    unsigned int u = __float_as_uint(v);
    asm("mov.b64 %0, {%1, %2};" : "=l"(r) : "r"(u), "r"(u));
    return r;
}
__device__ __forceinline__ unsigned long long fma2(unsigned long long a,
                                                   unsigned long long b,
                                                   unsigned long long c) {
    unsigned long long d;
    asm("fma.rn.f32x2 %0, %1, %2, %3;" : "=l"(d) : "l"(a), "l"(b), "l"(c));
    return d;
}
__device__ __forceinline__ float2 unpack2(unsigned long long v) {
    unsigned int lo, hi;
    asm("mov.b64 {%0, %1}, %2;" : "=r"(lo), "=r"(hi) : "l"(v));
    float2 f;
    f.x = __uint_as_float(lo);
    f.y = __uint_as_float(hi);
    return f;
}

// ---------------------------------------------------------------------------
// K0: probe edge_index element width (int64 buffer has high words zero ->
// first 32 int64 reads all land in [0, N); int32 buffer packs two random
// indices per read -> out of range with overwhelming probability).
// ---------------------------------------------------------------------------
__global__ void detect_kernel(const void* __restrict__ ei, int N) {
    if (threadIdx.x == 0 && blockIdx.x == 0) {
        const long long* p = (const long long*)ei;
        int ok = 1;
        for (int j = 0; j < 32; j++) {
            long long v = p[j];
            if (v < 0 || v >= (long long)N) { ok = 0; break; }
        }
        g_idx64 = ok;
    }
}

// ---------------------------------------------------------------------------
// K1: node transform h[n] = x[n] @ W_root + b_root  (also zero stats)
// ---------------------------------------------------------------------------
__global__ void node_kernel(const float* __restrict__ x,
                            const float* __restrict__ Wr,
                            const float* __restrict__ br, int N) {
    if (blockIdx.x == 0 && threadIdx.x < 2 * C_OUT) g_stats[threadIdx.x] = 0.f;
    int gid = blockIdx.x * NT + threadIdx.x;
    if (gid >= N * C_OUT) return;
    int n = gid >> 6;
    int c = gid & 63;
    const float* xr = x + (long long)n * C_IN;
    float acc = br[c];
#pragma unroll 16
    for (int i = 0; i < C_IN; i++) acc = fmaf(xr[i], Wr[i * C_OUT + c], acc);
    g_h[gid] = acc;
}

// ---------------------------------------------------------------------------
// K2: per-NODE message MLP (tile of 64 nodes per block)
//     msg[n] = relu(x[n] @ W1 + b1) @ W2 + b2
// smem layout (floats): W1[64*128] W2[128*64] X[64*68] H[64*132] b1[128] b2[64]
// ---------------------------------------------------------------------------
#define SX_PITCH 68
#define SH_PITCH 132
#define SMEM_FLOATS (8192 + 8192 + TILE_N * SX_PITCH + TILE_N * SH_PITCH + 128 + 64)
#define SMEM_BYTES (SMEM_FLOATS * 4)

__global__ __launch_bounds__(NT) void msg_kernel(
    const float* __restrict__ x, const float* __restrict__ W1,
    const float* __restrict__ b1, const float* __restrict__ W2,
    const float* __restrict__ b2, int N) {
    extern __shared__ float sm[];
    float* sW1 = sm;                      // 64 x 128
    float* sW2 = sW1 + 64 * 128;          // 128 x 64
    float* sX = sW2 + 128 * 64;           // 64 x 68 (padded)
    float* sH = sX + TILE_N * SX_PITCH;   // 64 x 132 (padded)
    float* sb1 = sH + TILE_N * SH_PITCH;  // 128
    float* sb2 = sb1 + 128;               // 64

    const int tid = threadIdx.x;
    const int n0 = blockIdx.x * TILE_N;

    // stage weights + biases
    for (int i = tid; i < 2048; i += NT)
        reinterpret_cast<float4*>(sW1)[i] = reinterpret_cast<const float4*>(W1)[i];
    for (int i = tid; i < 2048; i += NT)
        reinterpret_cast<float4*>(sW2)[i] = reinterpret_cast<const float4*>(W2)[i];
    if (tid < 128) sb1[tid] = b1[tid];
    if (tid < 64) sb2[tid] = b2[tid];

    // stage X tile (sequential rows, fully coalesced; clamp tail)
    for (int i = tid; i < TILE_N * 16; i += NT) {
        int r = i >> 4, q = i & 15;
        int n = n0 + r;
        if (n >= N) n = N - 1;
        float4 v = reinterpret_cast<const float4*>(x + (long long)n * C_IN)[q];
        *reinterpret_cast<float4*>(&sX[r * SX_PITCH + q * 4]) = v;
    }
    __syncthreads();

    // ---- GEMM1: H[64,128] = relu(X[64,64] @ W1[64,128] + b1) ----
    {
        const int hg = tid & 15;  // hidden group
        const int rg = tid >> 4;  // row group
        const int hb = hg * 8;
        const int rb = rg * 4;

        unsigned long long acc[4][4];
#pragma unroll
        for (int e = 0; e < 4; e++)
#pragma unroll
            for (int p = 0; p < 4; p++) acc[e][p] = 0ULL;

#pragma unroll 16
        for (int k = 0; k < C_IN; k++) {
            ulonglong2 w0 = *reinterpret_cast<const ulonglong2*>(&sW1[k * C_HID + hb]);
            ulonglong2 w1 = *reinterpret_cast<const ulonglong2*>(&sW1[k * C_HID + hb + 4]);
#pragma unroll
            for (int e = 0; e < 4; e++) {
                unsigned long long xp = pack2(sX[(rb + e) * SX_PITCH + k]);
                acc[e][0] = fma2(xp, w0.x, acc[e][0]);
                acc[e][1] = fma2(xp, w0.y, acc[e][1]);
                acc[e][2] = fma2(xp, w1.x, acc[e][2]);
                acc[e][3] = fma2(xp, w1.y, acc[e][3]);
            }
        }
#pragma unroll
        for (int e = 0; e < 4; e++) {
#pragma unroll
            for (int p = 0; p < 4; p++) {
                float2 v = unpack2(acc[e][p]);
                v.x = fmaxf(v.x + sb1[hb + 2 * p], 0.f);
                v.y = fmaxf(v.y + sb1[hb + 2 * p + 1], 0.f);
                *reinterpret_cast<float2*>(&sH[(rb + e) * SH_PITCH + hb + 2 * p]) = v;
            }
        }
    }
    __syncthreads();

    // ---- GEMM2: M[64,64] = H[64,128] @ W2[128,64] + b2 ; write to g_msg ----
    {
        const int kg = tid & 15;
        const int rg = tid >> 4;
        const int kb = kg * 4;
        const int rb = rg * 4;

        unsigned long long a2[4][2];
#pragma unroll
        for (int e = 0; e < 4; e++) {
            a2[e][0] = 0ULL;
            a2[e][1] = 0ULL;
        }

#pragma unroll 16
        for (int j = 0; j < C_HID; j++) {
            ulonglong2 w = *reinterpret_cast<const ulonglong2*>(&sW2[j * C_OUT + kb]);
#pragma unroll
            for (int e = 0; e < 4; e++) {
                unsigned long long hp = pack2(sH[(rb + e) * SH_PITCH + j]);
                a2[e][0] = fma2(hp, w.x, a2[e][0]);
                a2[e][1] = fma2(hp, w.y, a2[e][1]);
            }
        }

        float bx0 = sb2[kb], bx1 = sb2[kb + 1], bx2 = sb2[kb + 2], bx3 = sb2[kb + 3];
#pragma unroll
        for (int e = 0; e < 4; e++) {
            int n = n0 + rb + e;
            if (n >= N) continue;
            float2 v0 = unpack2(a2[e][0]);
            float2 v1 = unpack2(a2[e][1]);
            float4 r;
            r.x = v0.x + bx0;
            r.y = v0.y + bx1;
            r.z = v1.x + bx2;
            r.w = v1.y + bx3;
            *reinterpret_cast<float4*>(&g_msg[(long long)n * C_OUT + kb]) = r;
        }
    }
}

// ---------------------------------------------------------------------------
// K2b: scatter  g_h[dst] += msg[src]  (16 threads per edge, float4 each)
// ---------------------------------------------------------------------------
__global__ __launch_bounds__(NT) void scatter_kernel(const void* __restrict__ ei_raw,
                                                     int E) {
    long long idx = (long long)blockIdx.x * NT + threadIdx.x;
    long long total = (long long)E * 16;
    if (idx >= total) return;
    int e = (int)(idx >> 4);
    int q = (int)(idx & 15);
    int s, d;
    if (g_idx64) {
        const long long* p = (const long long*)ei_raw;
        s = (int)__ldg(&p[e]);
        d = (int)__ldg(&p[E + e]);
    } else {
        const int* p = (const int*)ei_raw;
        s = __ldg(&p[e]);
        d = __ldg(&p[E + e]);
    }
    float4 v = *reinterpret_cast<const float4*>(&g_msg[(long long)s * C_OUT + q * 4]);
    float* pd = &g_h[(long long)d * C_OUT + q * 4];
    asm volatile("red.global.add.v4.f32 [%0], {%1,%2,%3,%4};"
                 :: "l"(pd), "f"(v.x), "f"(v.y), "f"(v.z), "f"(v.w)
                 : "memory");
}

// ---------------------------------------------------------------------------
// K3: PReLU in-place + per-channel sum / sumsq partials
// (grid*block stride is a multiple of 64 -> each thread owns one channel)
// ---------------------------------------------------------------------------
__global__ void prelu_stats_kernel(const float* __restrict__ prelu_w, int N) {
    const float a = prelu_w[0];
    const int total = N * C_OUT;
    const int stride = gridDim.x * blockDim.x;
    float s = 0.f, ss = 0.f;
    for (int i = blockIdx.x * blockDim.x + threadIdx.x; i < total; i += stride) {
        float v = g_h[i];
        v = (v >= 0.f) ? v : a * v;
        g_h[i] = v;
        s += v;
        ss += v * v;
    }
    __shared__ float rs[NT], rss[NT];
    rs[threadIdx.x] = s;
    rss[threadIdx.x] = ss;
    __syncthreads();
    if (threadIdx.x < 64) {
        float ts = rs[threadIdx.x] + rs[threadIdx.x + 64] + rs[threadIdx.x + 128] +
                   rs[threadIdx.x + 192];
        float tss = rss[threadIdx.x] + rss[threadIdx.x + 64] + rss[threadIdx.x + 128] +
                    rss[threadIdx.x + 192];
        atomicAdd(&g_stats[threadIdx.x], ts);
        atomicAdd(&g_stats[64 + threadIdx.x], tss);
    }
}

// ---------------------------------------------------------------------------
// K4: finalize BN and write output
// ---------------------------------------------------------------------------
__global__ void bn_kernel(float* __restrict__ out, const float* __restrict__ gamma,
                          const float* __restrict__ beta, int N) {
    __shared__ float sscale[C_OUT], sshift[C_OUT];
    if (threadIdx.x < C_OUT) {
        float invN = 1.f / (float)N;
        float mu = g_stats[threadIdx.x] * invN;
        float var = g_stats[64 + threadIdx.x] * invN - mu * mu;
        float inv = rsqrtf(var + 1e-5f);
        float g = gamma[threadIdx.x] * inv;
        sscale[threadIdx.x] = g;
        sshift[threadIdx.x] = beta[threadIdx.x] - mu * g;
    }
    __syncthreads();
    const int total = N * C_OUT;
    const int stride = gridDim.x * blockDim.x;
    for (int i = blockIdx.x * blockDim.x + threadIdx.x; i < total; i += stride) {
        out[i] = g_h[i] * sscale[i & 63] + sshift[i & 63];
    }
}

// ---------------------------------------------------------------------------
extern "C" void kernel_launch(void* const* d_in, const int* in_sizes, int n_in,
                              void* d_out, int out_size) {
    const float* x = (const float*)d_in[0];
    const void* ei = d_in[1];
    const float* W1 = (const float*)d_in[2];
    const float* b1 = (const float*)d_in[3];
    const float* W2 = (const float*)d_in[4];
    const float* b2 = (const float*)d_in[5];
    const float* Wr = (const float*)d_in[6];
    const float* br = (const float*)d_in[7];
    const float* pw = (const float*)d_in[8];
    const float* gamma = (const float*)d_in[9];
    const float* beta = (const float*)d_in[10];
    float* out = (float*)d_out;

    const int N = in_sizes[0] / C_IN;
    const int E = in_sizes[1] / 2;

    cudaFuncSetAttribute(msg_kernel, cudaFuncAttributeMaxDynamicSharedMemorySize,
                         SMEM_BYTES);

    // K0: index dtype probe
    detect_kernel<<<1, 32>>>(ei, N);

    // K1: node transform (+ stats zero)
    node_kernel<<<(N * C_OUT + NT - 1) / NT, NT>>>(x, Wr, br, N);

    // K2: per-node message MLP
    const int numTiles = (N + TILE_N - 1) / TILE_N;
    msg_kernel<<<numTiles, NT, SMEM_BYTES>>>(x, W1, b1, W2, b2, N);

    // K2b: edge scatter (msg[src] -> h[dst])
    const long long units = (long long)E * 16;
    scatter_kernel<<<(int)((units + NT - 1) / NT), NT>>>(ei, E);

    // K3: PReLU + batch stats
    prelu_stats_kernel<<<592, NT>>>(pw, N);

    // K4: BN normalize -> out
    bn_kernel<<<592, NT>>>(out, gamma, beta, N);
}

// round 4
// speedup vs baseline: 8.0411x; 1.4009x over previous
#include <cuda_runtime.h>
#include <cstdint>

// ---------------------------------------------------------------------------
// GNBlock: h = BN(PReLU(segment_sum(relu(x[src]@W1+b1)@W2+b2, dst) + x@W_root + b_root))
// N=50000, E=800000, C_IN=64, C_HID=128, C_OUT=64
//
// msg = MLP(x[src]) depends only on src -> precompute per node (16x FLOP cut),
// scatter msg[src] -> h[dst] with red.global.add.v4. Root transform fused into
// the per-node MLP kernel (shares the staged X tile).
// ---------------------------------------------------------------------------

#define N_MAX 50000
#define C_IN 64
#define C_HID 128
#define C_OUT 64
#define TILE_N 128
#define MT 512
#define NT 256

__device__ __align__(16) float g_h[N_MAX * C_OUT];
__device__ __align__(16) float g_msg[N_MAX * C_OUT];
__device__ float g_stats[2 * C_OUT];  // [0:64) sum, [64:128) sumsq
__device__ int g_idx64;               // 1 if edge_index is int64, 0 if int32

// ---- f32x2 packed helpers (FFMA2, PTX-only on sm_103a) ----------------------
__device__ __forceinline__ unsigned long long pack2(float v) {
    unsigned long long r;
    unsigned int u = __float_as_uint(v);
    asm("mov.b64 %0, {%1, %2};" : "=l"(r) : "r"(u), "r"(u));
    return r;
}
__device__ __forceinline__ unsigned long long fma2(unsigned long long a,
                                                   unsigned long long b,
                                                   unsigned long long c) {
    unsigned long long d;
    asm("fma.rn.f32x2 %0, %1, %2, %3;" : "=l"(d) : "l"(a), "l"(b), "l"(c));
    return d;
}
__device__ __forceinline__ float2 unpack2(unsigned long long v) {
    unsigned int lo, hi;
    asm("mov.b64 {%0, %1}, %2;" : "=r"(lo), "=r"(hi) : "l"(v));
    float2 f;
    f.x = __uint_as_float(lo);
    f.y = __uint_as_float(hi);
    return f;
}

// ---------------------------------------------------------------------------
// K0: probe index width (32 parallel int64 reads + ballot) and zero stats.
// int64 buffer => high words zero => all reads in [0,N). int32 buffer packs
// two random indices per read => out of range w.p. ~1.
// ---------------------------------------------------------------------------
__global__ void detect_kernel(const void* __restrict__ ei, int N) {
    int tid = threadIdx.x;
    if (tid < 128) g_stats[tid] = 0.f;
    if (tid < 32) {
        const long long* p = (const long long*)ei;
        long long v = p[tid];
        unsigned ok = __ballot_sync(0xffffffffu, v >= 0 && v < (long long)N);
        if (tid == 0) g_idx64 = (ok == 0xffffffffu) ? 1 : 0;
    }
}

// ---------------------------------------------------------------------------
// K1: fused per-node kernel (tile of 128 nodes, 512 threads):
//   msg[n] = relu(x[n]@W1 + b1) @ W2 + b2     (GEMM1 -> sH -> GEMM2)
//   h[n]   = x[n]@W_root + b_root             (GEMM3, reuses sX)
// ---------------------------------------------------------------------------
#define SX_PITCH 68
#define SH_PITCH 132
#define SMEM_FLOATS (8192 + 8192 + 4096 + TILE_N * SX_PITCH + TILE_N * SH_PITCH + 256)
#define SMEM_BYTES (SMEM_FLOATS * 4)

__global__ __launch_bounds__(MT) void msg_kernel(
    const float* __restrict__ x, const float* __restrict__ W1,
    const float* __restrict__ b1, const float* __restrict__ W2,
    const float* __restrict__ b2, const float* __restrict__ Wr,
    const float* __restrict__ br, int N) {
    extern __shared__ float sm[];
    float* sW1 = sm;                      // 64 x 128
    float* sW2 = sW1 + 64 * 128;          // 128 x 64
    float* sWr = sW2 + 128 * 64;          // 64 x 64
    float* sX = sWr + 64 * 64;            // 128 x 68 (padded)
    float* sH = sX + TILE_N * SX_PITCH;   // 128 x 132 (padded)
    float* sb1 = sH + TILE_N * SH_PITCH;  // 128
    float* sb2 = sb1 + 128;               // 64
    float* sbr = sb2 + 64;                // 64

    const int tid = threadIdx.x;
    const int n0 = blockIdx.x * TILE_N;

    // stage weights + biases (float4)
    for (int i = tid; i < 2048; i += MT)
        reinterpret_cast<float4*>(sW1)[i] = reinterpret_cast<const float4*>(W1)[i];
    for (int i = tid; i < 2048; i += MT)
        reinterpret_cast<float4*>(sW2)[i] = reinterpret_cast<const float4*>(W2)[i];
    for (int i = tid; i < 1024; i += MT)
        reinterpret_cast<float4*>(sWr)[i] = reinterpret_cast<const float4*>(Wr)[i];
    if (tid < 128) sb1[tid] = b1[tid];
    else if (tid < 192) sb2[tid - 128] = b2[tid - 128];
    else if (tid < 256) sbr[tid - 192] = br[tid - 192];

    // stage X tile (coalesced; clamp tail)
    for (int i = tid; i < TILE_N * 16; i += MT) {
        int r = i >> 4, q = i & 15;
        int n = n0 + r;
        if (n >= N) n = N - 1;
        float4 v = reinterpret_cast<const float4*>(x + (long long)n * C_IN)[q];
        *reinterpret_cast<float4*>(&sX[r * SX_PITCH + q * 4]) = v;
    }
    __syncthreads();

    const int hg = tid & 15;   // col group
    const int rg = tid >> 4;   // row group (0..31)
    const int hb = hg * 8;     // GEMM1 hidden base
    const int kb = hg * 4;     // GEMM2/3 out-col base
    const int rb = rg * 4;     // row base

    // ---- GEMM1: H[128,128] = relu(X[128,64] @ W1 + b1), 4 rows x 8 hid ----
    {
        unsigned long long acc[4][4];
#pragma unroll
        for (int e = 0; e < 4; e++)
#pragma unroll
            for (int p = 0; p < 4; p++) acc[e][p] = 0ULL;

#pragma unroll 8
        for (int k = 0; k < C_IN; k += 2) {
            ulonglong2 wa0 = *reinterpret_cast<const ulonglong2*>(&sW1[k * C_HID + hb]);
            ulonglong2 wa1 = *reinterpret_cast<const ulonglong2*>(&sW1[k * C_HID + hb + 4]);
            ulonglong2 wb0 = *reinterpret_cast<const ulonglong2*>(&sW1[(k + 1) * C_HID + hb]);
            ulonglong2 wb1 = *reinterpret_cast<const ulonglong2*>(&sW1[(k + 1) * C_HID + hb + 4]);
#pragma unroll
            for (int e = 0; e < 4; e++) {
                float2 xv = *reinterpret_cast<const float2*>(&sX[(rb + e) * SX_PITCH + k]);
                unsigned long long x0 = pack2(xv.x), x1 = pack2(xv.y);
                acc[e][0] = fma2(x0, wa0.x, acc[e][0]);
                acc[e][1] = fma2(x0, wa0.y, acc[e][1]);
                acc[e][2] = fma2(x0, wa1.x, acc[e][2]);
                acc[e][3] = fma2(x0, wa1.y, acc[e][3]);
                acc[e][0] = fma2(x1, wb0.x, acc[e][0]);
                acc[e][1] = fma2(x1, wb0.y, acc[e][1]);
                acc[e][2] = fma2(x1, wb1.x, acc[e][2]);
                acc[e][3] = fma2(x1, wb1.y, acc[e][3]);
            }
        }
#pragma unroll
        for (int e = 0; e < 4; e++) {
#pragma unroll
            for (int p = 0; p < 4; p++) {
                float2 v = unpack2(acc[e][p]);
                v.x = fmaxf(v.x + sb1[hb + 2 * p], 0.f);
                v.y = fmaxf(v.y + sb1[hb + 2 * p + 1], 0.f);
                *reinterpret_cast<float2*>(&sH[(rb + e) * SH_PITCH + hb + 2 * p]) = v;
            }
        }
    }
    __syncthreads();

    // ---- GEMM3: h[128,64] = X @ W_root + b_root (reuses sX), 4 rows x 4 cols
    {
        unsigned long long a3[4][2];
#pragma unroll
        for (int e = 0; e < 4; e++) { a3[e][0] = 0ULL; a3[e][1] = 0ULL; }

#pragma unroll 8
        for (int k = 0; k < C_IN; k += 2) {
            ulonglong2 wa = *reinterpret_cast<const ulonglong2*>(&sWr[k * C_OUT + kb]);
            ulonglong2 wb = *reinterpret_cast<const ulonglong2*>(&sWr[(k + 1) * C_OUT + kb]);
#pragma unroll
            for (int e = 0; e < 4; e++) {
                float2 xv = *reinterpret_cast<const float2*>(&sX[(rb + e) * SX_PITCH + k]);
                unsigned long long x0 = pack2(xv.x), x1 = pack2(xv.y);
                a3[e][0] = fma2(x0, wa.x, a3[e][0]);
                a3[e][1] = fma2(x0, wa.y, a3[e][1]);
                a3[e][0] = fma2(x1, wb.x, a3[e][0]);
                a3[e][1] = fma2(x1, wb.y, a3[e][1]);
            }
        }
        float c0 = sbr[kb], c1 = sbr[kb + 1], c2 = sbr[kb + 2], c3 = sbr[kb + 3];
#pragma unroll
        for (int e = 0; e < 4; e++) {
            int n = n0 + rb + e;
            if (n >= N) continue;
            float2 v0 = unpack2(a3[e][0]);
            float2 v1 = unpack2(a3[e][1]);
            float4 r;
            r.x = v0.x + c0; r.y = v0.y + c1; r.z = v1.x + c2; r.w = v1.y + c3;
            *reinterpret_cast<float4*>(&g_h[(long long)n * C_OUT + kb]) = r;
        }
    }

    // ---- GEMM2: msg[128,64] = H @ W2 + b2, 4 rows x 4 cols ----
    {
        unsigned long long a2[4][2];
#pragma unroll
        for (int e = 0; e < 4; e++) { a2[e][0] = 0ULL; a2[e][1] = 0ULL; }

#pragma unroll 8
        for (int j = 0; j < C_HID; j += 2) {
            ulonglong2 wa = *reinterpret_cast<const ulonglong2*>(&sW2[j * C_OUT + kb]);
            ulonglong2 wb = *reinterpret_cast<const ulonglong2*>(&sW2[(j + 1) * C_OUT + kb]);
#pragma unroll
            for (int e = 0; e < 4; e++) {
                float2 hv = *reinterpret_cast<const float2*>(&sH[(rb + e) * SH_PITCH + j]);
                unsigned long long h0 = pack2(hv.x), h1 = pack2(hv.y);
                a2[e][0] = fma2(h0, wa.x, a2[e][0]);
                a2[e][1] = fma2(h0, wa.y, a2[e][1]);
                a2[e][0] = fma2(h1, wb.x, a2[e][0]);
                a2[e][1] = fma2(h1, wb.y, a2[e][1]);
            }
        }
        float c0 = sb2[kb], c1 = sb2[kb + 1], c2 = sb2[kb + 2], c3 = sb2[kb + 3];
#pragma unroll
        for (int e = 0; e < 4; e++) {
            int n = n0 + rb + e;
            if (n >= N) continue;
            float2 v0 = unpack2(a2[e][0]);
            float2 v1 = unpack2(a2[e][1]);
            float4 r;
            r.x = v0.x + c0; r.y = v0.y + c1; r.z = v1.x + c2; r.w = v1.y + c3;
            *reinterpret_cast<float4*>(&g_msg[(long long)n * C_OUT + kb]) = r;
        }
    }
}

// ---------------------------------------------------------------------------
// K2: scatter  g_h[dst] += msg[src]  (16 threads per edge, float4 each)
// ---------------------------------------------------------------------------
__global__ __launch_bounds__(NT) void scatter_kernel(const void* __restrict__ ei_raw,
                                                     int E) {
    long long idx = (long long)blockIdx.x * NT + threadIdx.x;
    long long total = (long long)E * 16;
    if (idx >= total) return;
    int e = (int)(idx >> 4);
    int q = (int)(idx & 15);
    int s, d;
    if (g_idx64) {
        const long long* p = (const long long*)ei_raw;
        s = (int)__ldg(&p[e]);
        d = (int)__ldg(&p[E + e]);
    } else {
        const int* p = (const int*)ei_raw;
        s = __ldg(&p[e]);
        d = __ldg(&p[E + e]);
    }
    float4 v = *reinterpret_cast<const float4*>(&g_msg[(long long)s * C_OUT + q * 4]);
    float* pd = &g_h[(long long)d * C_OUT + q * 4];
    asm volatile("red.global.add.v4.f32 [%0], {%1,%2,%3,%4};"
                 :: "l"(pd), "f"(v.x), "f"(v.y), "f"(v.z), "f"(v.w)
                 : "memory");
}

// ---------------------------------------------------------------------------
// K3: PReLU in-place (float4) + per-channel sum / sumsq partials
// ---------------------------------------------------------------------------
__global__ void prelu_stats_kernel(const float* __restrict__ prelu_w, int N) {
    const float a = prelu_w[0];
    const int total4 = N * (C_OUT / 4);
    const int stride = gridDim.x * blockDim.x;
    float4* gh4 = reinterpret_cast<float4*>(g_h);
    float s0 = 0.f, s1 = 0.f, s2 = 0.f, s3 = 0.f;
    float q0 = 0.f, q1 = 0.f, q2 = 0.f, q3 = 0.f;
    // stride is a multiple of 16 -> each thread touches a fixed channel quad
    for (int i = blockIdx.x * blockDim.x + threadIdx.x; i < total4; i += stride) {
        float4 v = gh4[i];
        v.x = (v.x >= 0.f) ? v.x : a * v.x;
        v.y = (v.y >= 0.f) ? v.y : a * v.y;
        v.z = (v.z >= 0.f) ? v.z : a * v.z;
        v.w = (v.w >= 0.f) ? v.w : a * v.w;
        gh4[i] = v;
        s0 += v.x; s1 += v.y; s2 += v.z; s3 += v.w;
        q0 += v.x * v.x; q1 += v.y * v.y; q2 += v.z * v.z; q3 += v.w * v.w;
    }
    __shared__ float rs[NT * 4], rq[NT * 4];
    int t = threadIdx.x;
    rs[t * 4 + 0] = s0; rs[t * 4 + 1] = s1; rs[t * 4 + 2] = s2; rs[t * 4 + 3] = s3;
    rq[t * 4 + 0] = q0; rq[t * 4 + 1] = q1; rq[t * 4 + 2] = q2; rq[t * 4 + 3] = q3;
    __syncthreads();
    if (t < 64) {
        // channel c = t ; contributions from threads with (tid&15) == c>>2
        int qq = t >> 2, comp = t & 3;
        float ts = 0.f, tq = 0.f;
#pragma unroll
        for (int m = 0; m < 16; m++) {
            int src = (m * 16 + qq) * 4 + comp;
            ts += rs[src];
            tq += rq[src];
        }
        atomicAdd(&g_stats[t], ts);
        atomicAdd(&g_stats[64 + t], tq);
    }
}

// ---------------------------------------------------------------------------
// K4: finalize BN and write output (float4)
// ---------------------------------------------------------------------------
__global__ void bn_kernel(float* __restrict__ out, const float* __restrict__ gamma,
                          const float* __restrict__ beta, int N) {
    __shared__ float sscale[C_OUT], sshift[C_OUT];
    if (threadIdx.x < C_OUT) {
        float invN = 1.f / (float)N;
        float mu = g_stats[threadIdx.x] * invN;
        float var = g_stats[64 + threadIdx.x] * invN - mu * mu;
        float inv = rsqrtf(var + 1e-5f);
        float g = gamma[threadIdx.x] * inv;
        sscale[threadIdx.x] = g;
        sshift[threadIdx.x] = beta[threadIdx.x] - mu * g;
    }
    __syncthreads();
    const int total4 = N * (C_OUT / 4);
    const int stride = gridDim.x * blockDim.x;
    const float4* gh4 = reinterpret_cast<const float4*>(g_h);
    float4* o4 = reinterpret_cast<float4*>(out);
    for (int i = blockIdx.x * blockDim.x + threadIdx.x; i < total4; i += stride) {
        int q = (i & 15);
        float4 sc = reinterpret_cast<const float4*>(sscale)[q];
        float4 sh = reinterpret_cast<const float4*>(sshift)[q];
        float4 v = gh4[i];
        float4 r;
        r.x = fmaf(v.x, sc.x, sh.x);
        r.y = fmaf(v.y, sc.y, sh.y);
        r.z = fmaf(v.z, sc.z, sh.z);
        r.w = fmaf(v.w, sc.w, sh.w);
        o4[i] = r;
    }
}

// ---------------------------------------------------------------------------
extern "C" void kernel_launch(void* const* d_in, const int* in_sizes, int n_in,
                              void* d_out, int out_size) {
    const float* x = (const float*)d_in[0];
    const void* ei = d_in[1];
    const float* W1 = (const float*)d_in[2];
    const float* b1 = (const float*)d_in[3];
    const float* W2 = (const float*)d_in[4];
    const float* b2 = (const float*)d_in[5];
    const float* Wr = (const float*)d_in[6];
    const float* br = (const float*)d_in[7];
    const float* pw = (const float*)d_in[8];
    const float* gamma = (const float*)d_in[9];
    const float* beta = (const float*)d_in[10];
    float* out = (float*)d_out;

    const int N = in_sizes[0] / C_IN;
    const int E = in_sizes[1] / 2;

    cudaFuncSetAttribute(msg_kernel, cudaFuncAttributeMaxDynamicSharedMemorySize,
                         SMEM_BYTES);

    // K0: index dtype probe + stats zero
    detect_kernel<<<1, 128>>>(ei, N);

    // K1: fused per-node MLP (msg) + root transform (h)
    const int numTiles = (N + TILE_N - 1) / TILE_N;
    msg_kernel<<<numTiles, MT, SMEM_BYTES>>>(x, W1, b1, W2, b2, Wr, br, N);

    // K2: edge scatter (msg[src] -> h[dst])
    const long long units = (long long)E * 16;
    scatter_kernel<<<(int)((units + NT - 1) / NT), NT>>>(ei, E);

    // K3: PReLU + batch stats
    prelu_stats_kernel<<<592, NT>>>(pw, N);

    // K4: BN normalize -> out
    bn_kernel<<<592, NT>>>(out, gamma, beta, N);
}